// round 16
// baseline (speedup 1.0000x reference)
#include <cuda_runtime.h>
#include <cuda_fp16.h>
#include <math.h>
#include <stdint.h>

#define N_NODES 200000
#define NSEG 1024
#define KP 40   // smem k-pitch (half elems): 80B rows -> conflict-free ldmatrix

// scratch (device globals: no allocation allowed)
__device__ float g_s[N_NODES];
__device__ float g_S[NSEG * 768];
__device__ float g_comb[NSEG * 768];
__device__ float g_h[NSEG * 512];
__device__ float g_cnt[NSEG * 3];
__device__ float g_part[4 * NSEG * 512];   // split-K partials (max 8MB)
__device__ __half g_Bh[8 * 5120];          // fp16(aw1), 8 chunk-tiles [n][kin] pitch KP
__device__ __half g_xh[(size_t)N_NODES * 256];  // fp16(x)

__device__ __forceinline__ uint32_t smem_u32(const void* p) {
    uint32_t a;
    asm("{ .reg .u64 t; cvta.to.shared.u64 t, %1; cvt.u32.u64 %0, t; }"
        : "=r"(a) : "l"(p));
    return a;
}
__device__ __forceinline__ void mma16816(float* d, const unsigned* a,
                                         const unsigned* b) {
    asm volatile(
        "mma.sync.aligned.m16n8k16.row.col.f32.f16.f16.f32 "
        "{%0,%1,%2,%3}, {%4,%5,%6,%7}, {%8,%9}, {%0,%1,%2,%3};"
        : "+f"(d[0]), "+f"(d[1]), "+f"(d[2]), "+f"(d[3])
        : "r"(a[0]), "r"(a[1]), "r"(a[2]), "r"(a[3]), "r"(b[0]), "r"(b[1]));
}
__device__ __forceinline__ void ldsm4(unsigned* r, uint32_t addr) {
    asm volatile(
        "ldmatrix.sync.aligned.m8n8.x4.shared.b16 {%0,%1,%2,%3}, [%4];"
        : "=r"(r[0]), "=r"(r[1]), "=r"(r[2]), "=r"(r[3]) : "r"(addr));
}
#define CP_COMMIT() asm volatile("cp.async.commit_group;" ::: "memory")

// ---------------------------------------------------------------------------
// K0: one-time fp16 quantization of aw1 into chunk-tiled [n][kin] images.
// ---------------------------------------------------------------------------
__global__ __launch_bounds__(256)
void k0_wsplit(const float* __restrict__ aw1) {
    int idx = blockIdx.x * 256 + threadIdx.x;
    int k = idx >> 7, n = idx & 127;
    int chunk = k >> 5, kin = k & 31;
    g_Bh[chunk * 5120 + n * KP + kin] = __float2half_rn(aw1[(size_t)k * 128 + n]);
}

// ---------------------------------------------------------------------------
// KC: x (fp32) -> g_xh (fp16), pure bandwidth kernel, 8 elems/thread.
// ---------------------------------------------------------------------------
__global__ __launch_bounds__(256)
void k_convert(const float* __restrict__ x) {
    size_t i = ((size_t)blockIdx.x * 256 + threadIdx.x) * 8;
    float4 a = *(const float4*)(x + i);
    float4 b = *(const float4*)(x + i + 4);
    __half2 h0 = __floats2half2_rn(a.x, a.y);
    __half2 h1 = __floats2half2_rn(a.z, a.w);
    __half2 h2 = __floats2half2_rn(b.x, b.y);
    __half2 h3 = __floats2half2_rn(b.z, b.w);
    *(uint4*)(g_xh + i) = make_uint4(*(unsigned*)&h0, *(unsigned*)&h1,
                                     *(unsigned*)&h2, *(unsigned*)&h3);
}

// ---------------------------------------------------------------------------
// K1: s[i] = tanh(x[i]@aw1 + ab1) @ aw2 + ab2, tensor-core path. (unchanged)
// ---------------------------------------------------------------------------
__global__ __launch_bounds__(256)
void k1_scores(const float* __restrict__ ab1, const float* __restrict__ aw2,
               const float* __restrict__ ab2) {
    extern __shared__ __align__(16) char smc[];
    __shared__ float red[8][32];

    int tid = threadIdx.x;
    int warp = tid >> 5, lane = tid & 31;
    int g = lane >> 2, tg = lane & 3;
    int warp_m = (warp >> 1) * 32, warp_n = (warp & 1) * 64;
    int m_base = blockIdx.x * 128;
    uint32_t sb = smem_u32(smc);

    int arow = lane & 15, akoff = (lane >> 4) * 8;
    int bnrow = ((lane >> 4) << 3) + (lane & 7), bkoff = ((lane >> 3) & 1) * 8;

    float acc[2][8][4];
#pragma unroll
    for (int a = 0; a < 2; a++)
#pragma unroll
        for (int b = 0; b < 8; b++)
#pragma unroll
            for (int c = 0; c < 4; c++) acc[a][b][c] = 0.f;

    {
        const uint4* src = (const uint4*)g_Bh;
        uint4* dst = (uint4*)(smc + 30720);
#pragma unroll
        for (int i = 0; i < 20; i++) dst[tid + i * 256] = src[tid + i * 256];
    }

    auto copyA = [&](int c, int s) {
        uint32_t stage = sb + s * 10240;
#pragma unroll
        for (int i = 0; i < 2; i++) {
            int o = tid + i * 256;
            int row = o >> 2, q = o & 3;
            int gm = m_base + row;
            const __half* src = g_xh + (size_t)gm * 256 + c * 32 + q * 8;
            uint32_t dst = stage + row * 80 + q * 16;
            int sz = (gm < N_NODES) ? 16 : 0;
            asm volatile("cp.async.cg.shared.global [%0], [%1], 16, %2;"
                         :: "r"(dst), "l"(src), "r"(sz) : "memory");
        }
        CP_COMMIT();
    };

    auto mmaChunk = [&](int c, int s) {
        uint32_t aB = sb + s * 10240;
        uint32_t bB = sb + 30720 + c * 10240;
#pragma unroll
        for (int kb = 0; kb < 2; kb++) {
            unsigned ah[2][4];
            ldsm4(ah[0], aB + (warp_m + arow) * 80 + (kb * 16 + akoff) * 2);
            ldsm4(ah[1], aB + (warp_m + 16 + arow) * 80 + (kb * 16 + akoff) * 2);
#pragma unroll
            for (int nbp = 0; nbp < 4; nbp++) {
                unsigned bb[4];
                ldsm4(bb, bB + (warp_n + nbp * 16 + bnrow) * 80 + (kb * 16 + bkoff) * 2);
#pragma unroll
                for (int mb = 0; mb < 2; mb++) {
                    mma16816(acc[mb][nbp * 2 + 0], ah[mb], bb + 0);
                    mma16816(acc[mb][nbp * 2 + 1], ah[mb], bb + 2);
                }
            }
        }
    };

    copyA(0, 0);
    copyA(1, 1);

#pragma unroll
    for (int c = 0; c < 8; c++) {
        if (c < 7) {
            asm volatile("cp.async.wait_group 1;" ::: "memory");
        } else {
            asm volatile("cp.async.wait_group 0;" ::: "memory");
        }
        __syncthreads();
        if (c < 6) copyA(c + 2, (c + 2) % 3);
        mmaChunk(c, c % 3);
    }

    float p[2][2] = {{0.f, 0.f}, {0.f, 0.f}};
#pragma unroll
    for (int mb = 0; mb < 2; mb++) {
#pragma unroll
        for (int nb = 0; nb < 8; nb++) {
            int n0 = warp_n + nb * 8 + tg * 2;
            float w0 = __ldg(aw2 + n0), w1 = __ldg(aw2 + n0 + 1);
            float bb0 = __ldg(ab1 + n0), bb1 = __ldg(ab1 + n0 + 1);
            p[mb][0] = fmaf(tanhf(acc[mb][nb][0] + bb0), w0, p[mb][0]);
            p[mb][0] = fmaf(tanhf(acc[mb][nb][1] + bb1), w1, p[mb][0]);
            p[mb][1] = fmaf(tanhf(acc[mb][nb][2] + bb0), w0, p[mb][1]);
            p[mb][1] = fmaf(tanhf(acc[mb][nb][3] + bb1), w1, p[mb][1]);
        }
    }
#pragma unroll
    for (int mb = 0; mb < 2; mb++)
#pragma unroll
        for (int h = 0; h < 2; h++) {
            p[mb][h] += __shfl_xor_sync(0xffffffffu, p[mb][h], 1);
            p[mb][h] += __shfl_xor_sync(0xffffffffu, p[mb][h], 2);
        }
    if (tg == 0) {
#pragma unroll
        for (int mb = 0; mb < 2; mb++) {
            red[warp][mb * 16 + g] = p[mb][0];
            red[warp][mb * 16 + g + 8] = p[mb][1];
        }
    }
    __syncthreads();
    if (tid < 128) {
        int row = tid;
        int mwi = row >> 5, rl = row & 31;
        float v = red[mwi * 2][rl] + red[mwi * 2 + 1][rl] + __ldg(ab2);
        int gm = m_base + row;
        if (gm < N_NODES) g_s[gm] = v;
    }
}

// ---------------------------------------------------------------------------
// K2: fused pooling, fp16 x (halved DRAM traffic). Prologue: max, z, counts.
// Main loop: stage 256 {e,type} coefs in smem, dependency-free accumulation.
// ---------------------------------------------------------------------------
__global__ __launch_bounds__(256)
void k2_pool(const int* __restrict__ batch, const int* __restrict__ mask) {
    __shared__ float rbuf[256];
    __shared__ float2 swt[256];
    __shared__ int sh_se[2];
    int seg = blockIdx.x, j = threadIdx.x;

    if (j < 2) {
        int target = seg + j;
        int lo = 0, hi = N_NODES;
        while (lo < hi) {
            int mid = (lo + hi) >> 1;
            if (batch[mid] < target) lo = mid + 1; else hi = mid;
        }
        sh_se[j] = lo;
    }
    __syncthreads();
    int start = sh_se[0], end = sh_se[1];

    // prologue pass 1: segment max of s
    float lm = -1e30f;
    for (int i = start + j; i < end; i += 256) lm = fmaxf(lm, g_s[i]);
    rbuf[j] = lm;
    __syncthreads();
#pragma unroll
    for (int o = 128; o > 0; o >>= 1) {
        if (j < o) rbuf[j] = fmaxf(rbuf[j], rbuf[j + o]);
        __syncthreads();
    }
    float m = rbuf[0];
    __syncthreads();

    // prologue pass 2: z and type counts
    float lz = 0.f, l1 = 0.f, l2 = 0.f;
    for (int i = start + j; i < end; i += 256) {
        lz += __expf(g_s[i] - m);
        int t1 = __ldg(mask + (size_t)i * 3 + 1);
        int t2 = __ldg(mask + (size_t)i * 3 + 2);
        if (t1) l1 += 1.f;
        else if (t2) l2 += 1.f;
    }
    float z, c1, c2;
    rbuf[j] = lz; __syncthreads();
#pragma unroll
    for (int o = 128; o > 0; o >>= 1) {
        if (j < o) rbuf[j] += rbuf[j + o];
        __syncthreads();
    }
    z = rbuf[0]; __syncthreads();
    rbuf[j] = l1; __syncthreads();
#pragma unroll
    for (int o = 128; o > 0; o >>= 1) {
        if (j < o) rbuf[j] += rbuf[j + o];
        __syncthreads();
    }
    c1 = rbuf[0]; __syncthreads();
    rbuf[j] = l2; __syncthreads();
#pragma unroll
    for (int o = 128; o > 0; o >>= 1) {
        if (j < o) rbuf[j] += rbuf[j + o];
        __syncthreads();
    }
    c2 = rbuf[0];
    if (j == 0) {
        float cnt = (float)(end - start);
        g_cnt[seg * 3 + 0] = cnt - c1 - c2;
        g_cnt[seg * 3 + 1] = c1;
        g_cnt[seg * 3 + 2] = c2;
    }
    __syncthreads();

    // main pooling loop (fp16 x)
    float acc = 0.f, S = 0.f, S1 = 0.f, S2 = 0.f;
    for (int blk = start; blk < end; blk += 256) {
        int n = end - blk; if (n > 256) n = 256;
        if (j < n) {
            int i = blk + j;
            float e = __expf(g_s[i] - m);
            int t1 = __ldg(mask + (size_t)i * 3 + 1);
            int t2 = __ldg(mask + (size_t)i * 3 + 2);
            float tf = t1 ? 1.f : (t2 ? 2.f : 0.f);
            swt[j] = make_float2(e, tf);
        }
        __syncthreads();
#pragma unroll 4
        for (int u = 0; u < n; u++) {
            float2 c = swt[u];
            float xv = __half2float(g_xh[(size_t)(blk + u) * 256 + j]);
            acc = fmaf(c.x, xv, acc);
            S += xv;
            S1 += (c.y == 1.f) ? xv : 0.f;
            S2 += (c.y == 2.f) ? xv : 0.f;
        }
        __syncthreads();
    }

    float cnt = (float)(end - start);
    size_t base = (size_t)seg * 768;
    g_comb[base + j]       = S / cnt;
    g_comb[base + 256 + j] = acc / z;
    g_S[base + j]       = S - S1 - S2;
    g_S[base + 256 + j] = S1;
    g_S[base + 512 + j] = S2;
}

// ---------------------------------------------------------------------------
// Split-K small GEMM partials: 64(M)x32(N) tiles, K-slice per blockIdx.z,
// double-buffered k32, NO bias (applied in epilogue). Writes g_part.
// ---------------------------------------------------------------------------
template <int EPI>
__global__ __launch_bounds__(256)
void gemm_part(const float* __restrict__ B0, const float* __restrict__ B1,
               const float* __restrict__ B2) {
    constexpr int N   = (EPI == 1) ? 512 : 256;
    constexpr int KS  = (EPI == 0) ? 128 : 192;   // K-slice length
    constexpr int lda = (EPI == 0) ? 512 : 768;
    constexpr int ldb = (EPI == 1) ? 512 : 256;

    const float* A = (EPI == 2) ? g_S : ((EPI == 1) ? g_comb : g_h);
    int ksplit = blockIdx.z;
    int koff = ksplit * KS;
    float* C = g_part + (size_t)ksplit * NSEG * N;

    __shared__ float As[2][32][64];
    __shared__ float Bs[2][32][32];
    int tid = threadIdx.x;
    int m_base = blockIdx.y * 64;
    int n_base = blockIdx.x * 32;

    float acc[2][4];
#pragma unroll
    for (int i = 0; i < 2; i++)
#pragma unroll
        for (int j = 0; j < 4; j++) acc[i][j] = 0.f;

    int m0 = (tid >> 3) << 1;
    int j0 = (tid & 7) << 2;

    int am = tid >> 2, ac = (tid & 3) << 2;
    int bk = tid >> 3, bc = (tid & 7) << 2;

    auto brow_ptr = [&](int kk) -> const float* {
        if (EPI == 2) {
            return (kk < 256) ? (B0 + (size_t)kk * ldb)
                 : (kk < 512) ? (B1 + (size_t)(kk - 256) * ldb)
                              : (B2 + (size_t)(kk - 512) * ldb);
        }
        return B0 + (size_t)kk * ldb;
    };

    float4 pa0 = *(const float4*)(A + (size_t)(m_base + am) * lda + koff + ac);
    float4 pa1 = *(const float4*)(A + (size_t)(m_base + am) * lda + koff + ac + 16);
    float4 pb  = *(const float4*)(brow_ptr(koff + bk) + n_base + bc);

    int buf = 0;
    As[0][ac + 0][am] = pa0.x; As[0][ac + 1][am] = pa0.y;
    As[0][ac + 2][am] = pa0.z; As[0][ac + 3][am] = pa0.w;
    As[0][ac + 16][am] = pa1.x; As[0][ac + 17][am] = pa1.y;
    As[0][ac + 18][am] = pa1.z; As[0][ac + 19][am] = pa1.w;
    *(float4*)&Bs[0][bk][bc] = pb;
    __syncthreads();

    for (int k0 = 0; k0 < KS; k0 += 32) {
        int kn = k0 + 32;
        if (kn < KS) {
            pa0 = *(const float4*)(A + (size_t)(m_base + am) * lda + koff + kn + ac);
            pa1 = *(const float4*)(A + (size_t)(m_base + am) * lda + koff + kn + ac + 16);
            pb  = *(const float4*)(brow_ptr(koff + kn + bk) + n_base + bc);
        }

#pragma unroll
        for (int k = 0; k < 32; k++) {
            float a0 = As[buf][k][m0], a1 = As[buf][k][m0 + 1];
            float4 bv = *(const float4*)&Bs[buf][k][j0];
            float b[4] = {bv.x, bv.y, bv.z, bv.w};
#pragma unroll
            for (int jj = 0; jj < 4; jj++) {
                acc[0][jj] = fmaf(a0, b[jj], acc[0][jj]);
                acc[1][jj] = fmaf(a1, b[jj], acc[1][jj]);
            }
        }

        if (kn < KS) {
            int nb = buf ^ 1;
            As[nb][ac + 0][am] = pa0.x; As[nb][ac + 1][am] = pa0.y;
            As[nb][ac + 2][am] = pa0.z; As[nb][ac + 3][am] = pa0.w;
            As[nb][ac + 16][am] = pa1.x; As[nb][ac + 17][am] = pa1.y;
            As[nb][ac + 18][am] = pa1.z; As[nb][ac + 19][am] = pa1.w;
            *(float4*)&Bs[nb][bk][bc] = pb;
        }
        __syncthreads();
        buf ^= 1;
    }

#pragma unroll
    for (int i = 0; i < 2; i++) {
        int m = m_base + m0 + i;
#pragma unroll
        for (int jj = 0; jj < 4; jj++) {
            int n = n_base + j0 + jj;
            C[(size_t)m * N + n] = acc[i][jj];
        }
    }
}

// ---------------------------------------------------------------------------
// Split-K epilogue: sum 4 partials + bias (+silu / +count*bias), write dest.
// ---------------------------------------------------------------------------
template <int EPI>
__global__ __launch_bounds__(256)
void gemm_epi(const float* __restrict__ bias0, const float* __restrict__ bias1,
              const float* __restrict__ bias2, float* __restrict__ Cout) {
    constexpr int N = (EPI == 1) ? 512 : 256;
    int idx = blockIdx.x * 256 + threadIdx.x;   // covers NSEG*N
    int m = idx / N, n = idx - m * N;
    float v = g_part[idx] + g_part[idx + NSEG * N] +
              g_part[idx + 2 * NSEG * N] + g_part[idx + 3 * NSEG * N];
    if (EPI == 0) {
        Cout[idx] = v + __ldg(bias0 + n);
    } else if (EPI == 1) {
        v += __ldg(bias0 + n);
        g_h[idx] = v / (1.f + __expf(-v));
    } else {
        v += g_cnt[m * 3 + 0] * __ldg(bias0 + n)
           + g_cnt[m * 3 + 1] * __ldg(bias1 + n)
           + g_cnt[m * 3 + 2] * __ldg(bias2 + n);
        g_comb[(size_t)m * 768 + 512 + n] = v;
    }
}

// ---------------------------------------------------------------------------
extern "C" void kernel_launch(void* const* d_in, const int* in_sizes, int n_in,
                              void* d_out, int out_size) {
    const float* x    = (const float*)d_in[0];
    const int*   batch = (const int*)d_in[1];
    const int*   mask  = (const int*)d_in[2];
    const float* aw1 = (const float*)d_in[4];
    const float* ab1 = (const float*)d_in[5];
    const float* aw2 = (const float*)d_in[6];
    const float* ab2 = (const float*)d_in[7];
    const float* we  = (const float*)d_in[8];
    const float* be  = (const float*)d_in[9];
    const float* wv  = (const float*)d_in[10];
    const float* bv  = (const float*)d_in[11];
    const float* wp  = (const float*)d_in[12];
    const float* bp  = (const float*)d_in[13];
    const float* w1  = (const float*)d_in[14];
    const float* b1  = (const float*)d_in[15];
    const float* w2  = (const float*)d_in[16];
    const float* b2  = (const float*)d_in[17];

    static bool attr_done = false;
    if (!attr_done) {
        cudaFuncSetAttribute(k1_scores,
                             cudaFuncAttributeMaxDynamicSharedMemorySize, 112640);
        attr_done = true;
    }

    k0_wsplit<<<128, 256>>>(aw1);
    k_convert<<<(N_NODES * 256) / (256 * 8), 256>>>(x);
    k1_scores<<<(N_NODES + 127) / 128, 256, 112640>>>(ab1, aw2, ab2);
    k2_pool<<<NSEG, 256>>>(batch, mask);

    gemm_part<2><<<dim3(8, 16, 4), 256>>>(we, wv, wp);
    gemm_epi<2><<<NSEG * 256 / 256, 256>>>(be, bv, bp, nullptr);
    gemm_part<1><<<dim3(16, 16, 4), 256>>>(w1, nullptr, nullptr);
    gemm_epi<1><<<NSEG * 512 / 256, 256>>>(b1, nullptr, nullptr, nullptr);
    gemm_part<0><<<dim3(8, 16, 4), 256>>>(w2, nullptr, nullptr);
    gemm_epi<0><<<NSEG * 256 / 256, 256>>>(b2, nullptr, nullptr, (float*)d_out);
}